// round 2
// baseline (speedup 1.0000x reference)
#include <cuda_runtime.h>
#include <cstdint>

// KSparseAutoencoder: B=4096, D=1024, L=16384, K=64, all fp32.
// Pipeline:
//   k_xbar:      xbar = x - b_dec                    (scratch, 16MB)
//   k_transpose: WdecT[l][d] = W_dec[d][l]           (scratch, 64MB)
//   k_encgemm:   a = xbar @ W_enc^T + b_enc  -> written into the f region of d_out
//                (fp32 FFMA2 packed-f32x2 GEMM, 128x128x16 tiles, 8x8 microtile)
//   k_topk:      per-row top-64 via threshold candidate filter + bitonic sort,
//                PLUS boundary refinement: candidates within +-DELTA of the
//                rank-64 value are re-ranked with exact fp64 dot products so the
//                selected index set matches the reference despite fp32 rounding.
//   k_scatter:   zero f row, scatter relu(vals) at selected indices
//   k_dec:       xhat = f @ W_dec^T + b_dec via the 64 (idx,val) pairs and WdecT

#define BB 4096
#define DD 1024
#define LL 16384
#define KK 64
#define DELTA 4e-5f

__device__ float g_xbar[(size_t)BB * DD];     // 16 MB
__device__ float g_WdecT[(size_t)LL * DD];    // 64 MB
__device__ float g_tv[BB * KK];               // relu'd top-k values
__device__ int   g_ti[BB * KK];               // top-k indices

// ---------------- packed f32x2 helpers (sm_103a FFMA2) ----------------
__device__ __forceinline__ unsigned long long pack2(float x, float y) {
    unsigned long long r;
    asm("mov.b64 %0, {%1, %2};" : "=l"(r) : "f"(x), "f"(y));
    return r;
}
__device__ __forceinline__ void unpack2(unsigned long long v, float& x, float& y) {
    asm("mov.b64 {%0, %1}, %2;" : "=f"(x), "=f"(y) : "l"(v));
}
__device__ __forceinline__ void ffma2(unsigned long long& d,
                                      unsigned long long a, unsigned long long b) {
    asm("fma.rn.f32x2 %0, %1, %2, %0;" : "+l"(d) : "l"(a), "l"(b));
}

// ---------------- xbar = x - b_dec ----------------
__global__ void k_xbar(const float4* __restrict__ x, const float4* __restrict__ bd) {
    int i = blockIdx.x * blockDim.x + threadIdx.x;
    if (i >= BB * DD / 4) return;
    float4 v = x[i];
    float4 b = bd[i & (DD / 4 - 1)];
    v.x -= b.x; v.y -= b.y; v.z -= b.z; v.w -= b.w;
    ((float4*)g_xbar)[i] = v;
}

// ---------------- transpose W_dec [D][L] -> WdecT [L][D] ----------------
__global__ void k_transpose(const float* __restrict__ W) {
    __shared__ float tile[32][33];
    int lx = blockIdx.x * 32 + threadIdx.x;   // L index
    int dy = blockIdx.y * 32 + threadIdx.y;   // D index
#pragma unroll
    for (int j = 0; j < 32; j += 8)
        tile[threadIdx.y + j][threadIdx.x] = W[(size_t)(dy + j) * LL + lx];
    __syncthreads();
    int dx = blockIdx.y * 32 + threadIdx.x;   // D index
    int ly = blockIdx.x * 32 + threadIdx.y;   // L index
#pragma unroll
    for (int j = 0; j < 32; j += 8)
        g_WdecT[(size_t)(ly + j) * DD + dx] = tile[threadIdx.x][threadIdx.y + j];
}

// ---------------- encoder GEMM: C[m][n] = sum_k A[m][k]*Bw[n][k] + be[n] ----------------
#define BM 128
#define BN 128
#define BKC 16
#define PADS 4

__global__ __launch_bounds__(256, 2)
void k_encgemm(const float* __restrict__ Bw, const float* __restrict__ be,
               float* __restrict__ C) {
    __shared__ float As[2][BKC][BM + PADS];
    __shared__ float Bs[2][BKC][BN + PADS];

    const int tid = threadIdx.x;
    const int tx = tid & 15;
    const int ty = tid >> 4;
    const int m0 = blockIdx.y * BM;
    const int n0 = blockIdx.x * BN;

    const float* Abase = g_xbar + (size_t)m0 * DD;
    const float* Bbase = Bw + (size_t)n0 * DD;

    int lrow[2], lcol[2];
#pragma unroll
    for (int i = 0; i < 2; i++) {
        int f4 = tid + 256 * i;
        lrow[i] = f4 >> 2;
        lcol[i] = (f4 & 3) * 4;
    }

    float4 ar[2], br[2];
#pragma unroll
    for (int i = 0; i < 2; i++) {
        ar[i] = *(const float4*)(Abase + (size_t)lrow[i] * DD + lcol[i]);
        br[i] = *(const float4*)(Bbase + (size_t)lrow[i] * DD + lcol[i]);
    }
#pragma unroll
    for (int i = 0; i < 2; i++) {
        As[0][lcol[i] + 0][lrow[i]] = ar[i].x;
        As[0][lcol[i] + 1][lrow[i]] = ar[i].y;
        As[0][lcol[i] + 2][lrow[i]] = ar[i].z;
        As[0][lcol[i] + 3][lrow[i]] = ar[i].w;
        Bs[0][lcol[i] + 0][lrow[i]] = br[i].x;
        Bs[0][lcol[i] + 1][lrow[i]] = br[i].y;
        Bs[0][lcol[i] + 2][lrow[i]] = br[i].z;
        Bs[0][lcol[i] + 3][lrow[i]] = br[i].w;
    }
    __syncthreads();

    unsigned long long acc[8][4];
#pragma unroll
    for (int i = 0; i < 8; i++)
#pragma unroll
        for (int j = 0; j < 4; j++) acc[i][j] = 0ULL;

    const int nch = DD / BKC;  // 64
    for (int ch = 0; ch < nch; ch++) {
        const int cur = ch & 1;
        if (ch + 1 < nch) {
            const int k0 = (ch + 1) * BKC;
#pragma unroll
            for (int i = 0; i < 2; i++) {
                ar[i] = *(const float4*)(Abase + (size_t)lrow[i] * DD + k0 + lcol[i]);
                br[i] = *(const float4*)(Bbase + (size_t)lrow[i] * DD + k0 + lcol[i]);
            }
        }
#pragma unroll
        for (int k = 0; k < BKC; k++) {
            float4 a0 = *(const float4*)&As[cur][k][ty * 8];
            float4 a1 = *(const float4*)&As[cur][k][ty * 8 + 4];
            float4 b0 = *(const float4*)&Bs[cur][k][tx * 8];
            float4 b1 = *(const float4*)&Bs[cur][k][tx * 8 + 4];
            unsigned long long bp[4] = {pack2(b0.x, b0.y), pack2(b0.z, b0.w),
                                        pack2(b1.x, b1.y), pack2(b1.z, b1.w)};
            float am[8] = {a0.x, a0.y, a0.z, a0.w, a1.x, a1.y, a1.z, a1.w};
#pragma unroll
            for (int i = 0; i < 8; i++) {
                unsigned long long ap = pack2(am[i], am[i]);
#pragma unroll
                for (int j = 0; j < 4; j++) ffma2(acc[i][j], ap, bp[j]);
            }
        }
        if (ch + 1 < nch) {
            __syncthreads();
            const int nxt = (ch + 1) & 1;
#pragma unroll
            for (int i = 0; i < 2; i++) {
                As[nxt][lcol[i] + 0][lrow[i]] = ar[i].x;
                As[nxt][lcol[i] + 1][lrow[i]] = ar[i].y;
                As[nxt][lcol[i] + 2][lrow[i]] = ar[i].z;
                As[nxt][lcol[i] + 3][lrow[i]] = ar[i].w;
                Bs[nxt][lcol[i] + 0][lrow[i]] = br[i].x;
                Bs[nxt][lcol[i] + 1][lrow[i]] = br[i].y;
                Bs[nxt][lcol[i] + 2][lrow[i]] = br[i].z;
                Bs[nxt][lcol[i] + 3][lrow[i]] = br[i].w;
            }
            __syncthreads();
        }
    }

    float4 be0 = *(const float4*)(be + n0 + tx * 8);
    float4 be1 = *(const float4*)(be + n0 + tx * 8 + 4);
#pragma unroll
    for (int i = 0; i < 8; i++) {
        float c[8];
        unpack2(acc[i][0], c[0], c[1]);
        unpack2(acc[i][1], c[2], c[3]);
        unpack2(acc[i][2], c[4], c[5]);
        unpack2(acc[i][3], c[6], c[7]);
        c[0] += be0.x; c[1] += be0.y; c[2] += be0.z; c[3] += be0.w;
        c[4] += be1.x; c[5] += be1.y; c[6] += be1.z; c[7] += be1.w;
        float* crow = C + (size_t)(m0 + ty * 8 + i) * LL + n0 + tx * 8;
        *(float4*)(crow)     = make_float4(c[0], c[1], c[2], c[3]);
        *(float4*)(crow + 4) = make_float4(c[4], c[5], c[6], c[7]);
    }
}

// ---------------- per-row top-64 with fp64 boundary refinement ----------------
#define NTH 16
#define NCAND 1024
#define BANDCAP 64

__device__ __forceinline__ float key_val(unsigned long long kk) {
    unsigned u = (unsigned)(kk >> 32);
    unsigned bits = (u & 0x80000000u) ? (u & 0x7FFFFFFFu) : ~u;
    return __uint_as_float(bits);
}
__device__ __forceinline__ int key_idx(unsigned long long kk) {
    return (int)(0xFFFFFFFFu - (unsigned)(kk & 0xFFFFFFFFu));
}

__global__ __launch_bounds__(256)
void k_topk(const float* __restrict__ a, const float* __restrict__ W_enc,
            const float* __restrict__ b_enc) {
    const int row = blockIdx.x;
    const int tid = threadIdx.x;
    const float* r = a + (size_t)row * LL;

    __shared__ unsigned long long keys[NCAND];
    __shared__ int s_cnt[NTH];
    __shared__ int s_n;
    __shared__ float s_t;

    const float T[NTH] = {3.6f, 3.2f, 2.9f, 2.65f, 2.45f, 2.25f, 2.05f, 1.85f,
                          1.6f, 1.3f, 1.0f, 0.7f, 0.4f, 0.15f, -0.2f, -1e30f};

    if (tid < NTH) s_cnt[tid] = 0;
    if (tid == 0) s_n = 0;
    __syncthreads();

    int cnt[NTH];
#pragma unroll
    for (int t = 0; t < NTH; t++) cnt[t] = 0;
    for (int i = tid; i < LL; i += 256) {
        float v = r[i];
#pragma unroll
        for (int t = 0; t < NTH; t++) cnt[t] += (v > T[t]) ? 1 : 0;
    }
#pragma unroll
    for (int t = 0; t < NTH; t++) {
        int c = cnt[t];
#pragma unroll
        for (int o = 16; o > 0; o >>= 1) c += __shfl_down_sync(0xffffffffu, c, o);
        if ((tid & 31) == 0) atomicAdd(&s_cnt[t], c);
    }
    __syncthreads();
    if (tid == 0) {
        int sel = NTH - 1;
        for (int t = 0; t < NTH; t++) {
            if (s_cnt[t] >= KK) { sel = t; break; }
        }
        s_t = T[sel];
    }
    __syncthreads();

    const float th = s_t;
    for (int i = tid; i < LL; i += 256) {
        float v = r[i];
        if (v > th) {
            int p = atomicAdd(&s_n, 1);
            if (p < NCAND) {
                unsigned u = __float_as_uint(v);
                u = (u & 0x80000000u) ? ~u : (u | 0x80000000u);
                keys[p] = ((unsigned long long)u << 32) |
                          (unsigned long long)(0xFFFFFFFFu - (unsigned)i);
            }
        }
    }
    __syncthreads();
    int n = s_n; if (n > NCAND) n = NCAND;
    for (int i = n + tid; i < NCAND; i += 256) keys[i] = 0ULL;
    __syncthreads();

    // bitonic sort ascending
    for (int size = 2; size <= NCAND; size <<= 1) {
        for (int stride = size >> 1; stride > 0; stride >>= 1) {
            for (int i = tid; i < NCAND; i += 256) {
                int j = i ^ stride;
                if (j > i) {
                    bool asc = ((i & size) == 0);
                    unsigned long long x = keys[i], y = keys[j];
                    if ((x > y) == asc) { keys[i] = y; keys[j] = x; }
                }
            }
            __syncthreads();
        }
    }

    // ---- boundary refinement ----
    __shared__ float s_hi, s_lo;
    __shared__ int s_certain, s_bandN;
    __shared__ int   bandIdx[BANDCAP];
    __shared__ float bandVal[BANDCAP];
    __shared__ double bandD[BANDCAP];
    __shared__ int pickSlot[KK];
    __shared__ double s_red[8];

    if (tid == 0) {
        float v64 = key_val(keys[NCAND - KK]);
        s_hi = v64 + DELTA;
        s_lo = v64 - DELTA;
        s_certain = 0;
        s_bandN = 0;
    }
    __syncthreads();
    const float hiv = s_hi, lov = s_lo;

    int certLocal = 0;
    for (int i = tid; i < LL; i += 256) {
        float v = r[i];
        if (v > hiv) certLocal++;
        else if (v > lov) {
            int p = atomicAdd(&s_bandN, 1);
            if (p < BANDCAP) { bandIdx[p] = i; bandVal[p] = v; }
        }
    }
    {
        int c = certLocal;
#pragma unroll
        for (int o = 16; o > 0; o >>= 1) c += __shfl_down_sync(0xffffffffu, c, o);
        if ((tid & 31) == 0) atomicAdd(&s_certain, c);
    }
    __syncthreads();

    const int certain = s_certain;
    int bandN = s_bandN; if (bandN > BANDCAP) bandN = BANDCAP;
    const int need = KK - certain;

    if (bandN == need || need < 0 || need > bandN) {
        // unambiguous (or degenerate fallback): selection = top-64 of sorted candidates
        if (tid < KK) {
            unsigned long long kk = keys[NCAND - 1 - tid];
            float v = key_val(kk);
            g_tv[row * KK + tid] = v > 0.f ? v : 0.f;
            g_ti[row * KK + tid] = key_idx(kk);
        }
        return;
    }

    // ambiguous: make band ordering deterministic (sort by index, thread 0, tiny N)
    if (tid == 0) {
        for (int i = 1; i < bandN; i++) {
            int ki = bandIdx[i]; float kv = bandVal[i];
            int j = i - 1;
            while (j >= 0 && bandIdx[j] > ki) {
                bandIdx[j + 1] = bandIdx[j]; bandVal[j + 1] = bandVal[j]; j--;
            }
            bandIdx[j + 1] = ki; bandVal[j + 1] = kv;
        }
    }
    __syncthreads();

    // exact fp64 dot product for each band candidate
    const float* xb = g_xbar + (size_t)row * DD;
    for (int c = 0; c < bandN; c++) {
        const float* wrow = W_enc + (size_t)bandIdx[c] * DD;
        double part = 0.0;
        for (int d = tid * 4; d < DD; d += 256 * 4) {
            part += (double)xb[d + 0] * (double)wrow[d + 0]
                  + (double)xb[d + 1] * (double)wrow[d + 1]
                  + (double)xb[d + 2] * (double)wrow[d + 2]
                  + (double)xb[d + 3] * (double)wrow[d + 3];
        }
#pragma unroll
        for (int o = 16; o > 0; o >>= 1) part += __shfl_down_sync(0xffffffffu, part, o);
        if ((tid & 31) == 0) s_red[tid >> 5] = part;
        __syncthreads();
        if (tid == 0) {
            double tot = 0.0;
            for (int w = 0; w < 8; w++) tot += s_red[w];
            bandD[c] = tot + (double)b_enc[bandIdx[c]];
        }
        __syncthreads();
    }

    // thread 0: pick 'need' largest by (fp64 value desc, index asc)
    if (tid == 0) {
        unsigned taken = 0;  // bandN <= 64 -> use two words
        unsigned taken2 = 0;
        for (int p = 0; p < need; p++) {
            int best = -1;
            for (int c = 0; c < bandN; c++) {
                bool used = (c < 32) ? ((taken >> c) & 1u) : ((taken2 >> (c - 32)) & 1u);
                if (used) continue;
                if (best < 0 || bandD[c] > bandD[best]) best = c;  // idx-sorted: > keeps smaller idx on tie
            }
            if (best < 32) taken |= 1u << best; else taken2 |= 1u << (best - 32);
            pickSlot[p] = best;
        }
    }
    __syncthreads();

    // write result: first `certain` from sorted candidates, rest from band picks
    if (tid < KK) {
        float v; int idx;
        if (tid < certain) {
            unsigned long long kk = keys[NCAND - 1 - tid];
            v = key_val(kk); idx = key_idx(kk);
        } else {
            int c = pickSlot[tid - certain];
            v = bandVal[c]; idx = bandIdx[c];
        }
        g_tv[row * KK + tid] = v > 0.f ? v : 0.f;
        g_ti[row * KK + tid] = idx;
    }
}

// ---------------- f: zero row + scatter relu(vals) ----------------
__global__ void k_scatter(float* __restrict__ f) {
    const int row = blockIdx.x;
    float4* fr = (float4*)(f + (size_t)row * LL);
    for (int i = threadIdx.x; i < LL / 4; i += blockDim.x)
        fr[i] = make_float4(0.f, 0.f, 0.f, 0.f);
    __syncthreads();
    if (threadIdx.x < KK) {
        f[(size_t)row * LL + g_ti[row * KK + threadIdx.x]] = g_tv[row * KK + threadIdx.x];
    }
}

// ---------------- decoder: xhat[b][:] = b_dec + sum_j val_j * WdecT[idx_j][:] ----------------
__global__ __launch_bounds__(256)
void k_dec(const float* __restrict__ b_dec, float* __restrict__ xhat) {
    const int row = blockIdx.x;
    const int tid = threadIdx.x;
    __shared__ float sv[KK];
    __shared__ int si[KK];
    if (tid < KK) {
        sv[tid] = g_tv[row * KK + tid];
        si[tid] = g_ti[row * KK + tid];
    }
    __syncthreads();
    float4 acc = ((const float4*)b_dec)[tid];
#pragma unroll 4
    for (int j = 0; j < KK; j++) {
        float v = sv[j];
        float4 w = ((const float4*)(g_WdecT + (size_t)si[j] * DD))[tid];
        acc.x += v * w.x; acc.y += v * w.y; acc.z += v * w.z; acc.w += v * w.w;
    }
    ((float4*)(xhat + (size_t)row * DD))[tid] = acc;
}

// ---------------- launcher ----------------
extern "C" void kernel_launch(void* const* d_in, const int* in_sizes, int n_in,
                              void* d_out, int out_size) {
    const float* x     = (const float*)d_in[0];
    const float* W_enc = (const float*)d_in[1];
    const float* b_enc = (const float*)d_in[2];
    const float* W_dec = (const float*)d_in[3];
    const float* b_dec = (const float*)d_in[4];
    float* f    = (float*)d_out;
    float* xhat = f + (size_t)BB * LL;

    k_xbar<<<(BB * DD / 4 + 255) / 256, 256>>>((const float4*)x, (const float4*)b_dec);
    k_transpose<<<dim3(LL / 32, DD / 32), dim3(32, 8)>>>(W_dec);
    k_encgemm<<<dim3(LL / BN, BB / BM), 256>>>(W_enc, b_enc, f);
    k_topk<<<BB, 256>>>(f, W_enc, b_enc);
    k_scatter<<<BB, 256>>>(f);
    k_dec<<<BB, 256>>>(b_dec, xhat);
}

// round 4
// speedup vs baseline: 2.5391x; 2.5391x over previous
#include <cuda_runtime.h>
#include <cuda_fp16.h>
#include <cstdint>

// KSparseAutoencoder: B=4096, D=1024, L=16384, K=64, fp32 in/out.
// R4: encoder GEMM via mma.sync.m16n8k16 fp16 (legacy HMMA — tcgen05 PTX is
// rejected by the harness's compute_103 virtual arch). Two-term fp16 split with
// scaled residual folded into one K=2048 GEMM; top-64 with fp64 boundary
// refinement (DELTA = 1e-3 covers the 1.2e-4 split error).

#define BB 4096
#define DD 1024
#define LL 16384
#define KK 64
#define KTOT 2048
#define DELTA 1e-3f

__device__ float g_xbar[(size_t)BB * DD];        // 16 MB exact (fp64 refine)
__device__ __half g_A2[(size_t)BB * KTOT];       // 16 MB [xhi | xhi*2^-10]
__device__ __half g_B2[(size_t)LL * KTOT];       // 64 MB [Whi | Wlo*2^10]
__device__ float g_WdecT[(size_t)LL * DD];       // 64 MB
__device__ float g_tv[BB * KK];
__device__ int   g_ti[BB * KK];

// ==================== helpers ====================
__device__ __forceinline__ uint32_t smem_u32(const void* p) {
    uint32_t a;
    asm("{ .reg .u64 t; cvta.to.shared.u64 t, %1; cvt.u32.u64 %0, t; }" : "=r"(a) : "l"(p));
    return a;
}
__device__ __forceinline__ void cp16(uint32_t dst, const void* src) {
    asm volatile("cp.async.cg.shared.global [%0], [%1], 16;" :: "r"(dst), "l"(src));
}
__device__ __forceinline__ void cp_commit() { asm volatile("cp.async.commit_group;"); }
__device__ __forceinline__ void cp_wait1()  { asm volatile("cp.async.wait_group 1;" ::: "memory"); }

__device__ __forceinline__ void ldsm_x4(uint32_t* r, uint32_t addr) {
    asm volatile("ldmatrix.sync.aligned.m8n8.x4.shared.b16 {%0,%1,%2,%3}, [%4];"
                 : "=r"(r[0]), "=r"(r[1]), "=r"(r[2]), "=r"(r[3]) : "r"(addr));
}
__device__ __forceinline__ void mma16816(float* c, const uint32_t* a, uint32_t b0, uint32_t b1) {
    asm volatile("mma.sync.aligned.m16n8k16.row.col.f32.f16.f16.f32 "
                 "{%0,%1,%2,%3}, {%4,%5,%6,%7}, {%8,%9}, {%0,%1,%2,%3};"
                 : "+f"(c[0]), "+f"(c[1]), "+f"(c[2]), "+f"(c[3])
                 : "r"(a[0]), "r"(a[1]), "r"(a[2]), "r"(a[3]), "r"(b0), "r"(b1));
}

// ==================== prep kernels ====================
__global__ void k_prep_a(const float* __restrict__ x, const float* __restrict__ bd) {
    int i = blockIdx.x * blockDim.x + threadIdx.x;
    if (i >= BB * DD) return;
    int d = i & (DD - 1);
    int m = i >> 10;
    float xb = x[i] - bd[d];
    g_xbar[i] = xb;
    __half hi = __float2half_rn(xb);
    float hif = __half2float(hi);
    g_A2[(size_t)m * KTOT + d] = hi;
    g_A2[(size_t)m * KTOT + DD + d] = __float2half_rn(hif * 0.0009765625f);  // *2^-10 exact
}

__global__ void k_prep_b(const float* __restrict__ W) {
    int i = blockIdx.x * blockDim.x + threadIdx.x;
    if (i >= LL * DD) return;
    int d = i & (DD - 1);
    int n = i >> 10;
    float w = W[i];
    __half hi = __float2half_rn(w);
    float rem = w - __half2float(hi);
    g_B2[(size_t)n * KTOT + d] = hi;
    g_B2[(size_t)n * KTOT + DD + d] = __float2half_rn(rem * 1024.0f);        // *2^10
}

// ---------------- transpose W_dec [D][L] -> WdecT [L][D] ----------------
__global__ void k_transpose(const float* __restrict__ W) {
    __shared__ float tile[32][33];
    int lx = blockIdx.x * 32 + threadIdx.x;
    int dy = blockIdx.y * 32 + threadIdx.y;
#pragma unroll
    for (int j = 0; j < 32; j += 8)
        tile[threadIdx.y + j][threadIdx.x] = W[(size_t)(dy + j) * LL + lx];
    __syncthreads();
    int dx = blockIdx.y * 32 + threadIdx.x;
    int ly = blockIdx.x * 32 + threadIdx.y;
#pragma unroll
    for (int j = 0; j < 32; j += 8)
        g_WdecT[(size_t)(ly + j) * DD + dx] = tile[threadIdx.x][threadIdx.y + j];
}

// ==================== fp16 mma.sync GEMM ====================
// C[4096][16384] = A2 @ B2^T + b_enc, K=2048, 64 k-stages of 32.
#define GM 128
#define GN 256
#define GK 32
#define NSTG 64                       // KTOT/GK
#define ASTR 40                       // smem row stride in halves (32+8 pad)
#define A_BYTES (GM * ASTR * 2)       // 10240
#define B_BYTES (GN * ASTR * 2)       // 20480
#define STG_BYTES (A_BYTES + B_BYTES) // 30720
#define GSMEM (3 * STG_BYTES)         // 92160

__global__ __launch_bounds__(512, 1)
void k_gemm(const float* __restrict__ be, float* __restrict__ C) {
    extern __shared__ __align__(128) char smem[];
    const uint32_t sb = smem_u32(smem);
    const int tid = threadIdx.x;
    const int lane = tid & 31;
    const int wid = tid >> 5;
    const int wm = wid >> 3;          // 0..1  (64-row slabs)
    const int wn = wid & 7;           // 0..7  (32-col slabs)
    const int m0 = blockIdx.x * GM;
    const int n0 = blockIdx.y * GN;

    const __half* Ag = g_A2 + (size_t)m0 * KTOT;
    const __half* Bg = g_B2 + (size_t)n0 * KTOT;

    const int arow = tid >> 2, aseg = tid & 3;          // A: 512 cp16
    auto load_stage = [&](int s, int buf) {
        uint32_t ab = sb + buf * STG_BYTES;
        uint32_t bb = ab + A_BYTES;
        const __half* Ak = Ag + s * GK;
        const __half* Bk = Bg + s * GK;
        cp16(ab + arow * 80 + aseg * 16, Ak + (size_t)arow * KTOT + aseg * 8);
#pragma unroll
        for (int i = 0; i < 2; i++) {                    // B: 1024 cp16
            int idx = tid + i * 512;
            int row = idx >> 2, seg = idx & 3;
            cp16(bb + row * 80 + seg * 16, Bk + (size_t)row * KTOT + seg * 8);
        }
        cp_commit();
    };

    float acc[4][4][4];
#pragma unroll
    for (int i = 0; i < 4; i++)
#pragma unroll
        for (int j = 0; j < 4; j++)
#pragma unroll
            for (int q = 0; q < 4; q++) acc[i][j][q] = 0.f;

    load_stage(0, 0);
    load_stage(1, 1);

    const int wm64 = wm * 64;
    const int wn32 = wn * 32;
    for (int s = 0; s < NSTG; s++) {
        const int buf = s % 3;
        cp_wait1();
        __syncthreads();
        if (s + 2 < NSTG) load_stage(s + 2, (s + 2) % 3);

        uint32_t ab = sb + buf * STG_BYTES;
        uint32_t bb = ab + A_BYTES;
#pragma unroll
        for (int ks = 0; ks < 2; ks++) {
            const int k0 = ks * 16;
            uint32_t ra[4][4], rb[2][4];
#pragma unroll
            for (int mt = 0; mt < 4; mt++)
                ldsm_x4(ra[mt], ab + (uint32_t)(wm64 + mt * 16 + (lane & 15)) * 80
                                    + (uint32_t)(k0 + ((lane >> 4) << 3)) * 2);
#pragma unroll
            for (int g = 0; g < 2; g++)
                ldsm_x4(rb[g], bb + (uint32_t)(wn32 + g * 16 + (lane & 7) + ((lane & 16) >> 1)) * 80
                                   + (uint32_t)k0 * 2 + ((lane & 8) << 1));
#pragma unroll
            for (int mt = 0; mt < 4; mt++)
#pragma unroll
                for (int nt = 0; nt < 4; nt++)
                    mma16816(acc[mt][nt], ra[mt], rb[nt >> 1][(nt & 1) * 2],
                             rb[nt >> 1][(nt & 1) * 2 + 1]);
        }
    }

    // epilogue: c0,c1 -> (row l/4, col (l%4)*2); c2,c3 -> row +8
    const int cq = (lane & 3) * 2;
    const int rq = lane >> 2;
#pragma unroll
    for (int nt = 0; nt < 4; nt++) {
        const int col = n0 + wn32 + nt * 8 + cq;
        const float2 bev = *(const float2*)(be + col);
#pragma unroll
        for (int mt = 0; mt < 4; mt++) {
            const int row = m0 + wm64 + mt * 16 + rq;
            float2 v0 = make_float2(acc[mt][nt][0] + bev.x, acc[mt][nt][1] + bev.y);
            float2 v1 = make_float2(acc[mt][nt][2] + bev.x, acc[mt][nt][3] + bev.y);
            *(float2*)(C + (size_t)row * LL + col) = v0;
            *(float2*)(C + (size_t)(row + 8) * LL + col) = v1;
        }
    }
}

// ==================== per-row top-64 ====================
#define NCAND 1024
#define BANDCAP 64

__device__ __forceinline__ float key_val(unsigned long long kk) {
    unsigned u = (unsigned)(kk >> 32);
    unsigned bits = (u & 0x80000000u) ? (u & 0x7FFFFFFFu) : ~u;
    return __uint_as_float(bits);
}
__device__ __forceinline__ int key_idx(unsigned long long kk) {
    return (int)(0xFFFFFFFFu - (unsigned)(kk & 0xFFFFFFFFu));
}
__device__ __forceinline__ unsigned long long mk_key(float v, int i) {
    unsigned u = __float_as_uint(v);
    u = (u & 0x80000000u) ? ~u : (u | 0x80000000u);
    return ((unsigned long long)u << 32) | (unsigned long long)(0xFFFFFFFFu - (unsigned)i);
}

__global__ __launch_bounds__(256)
void k_topk(const float* __restrict__ a, const float* __restrict__ W_enc,
            const float* __restrict__ b_enc) {
    const int row = blockIdx.x;
    const int tid = threadIdx.x;
    const float* r = a + (size_t)row * LL;
    const float4* r4 = (const float4*)r;

    __shared__ unsigned long long keys[NCAND];
    __shared__ int s_n;

    const float ladder[8] = {3.4f, 2.8f, 2.3f, 2.0f, 1.65f, 1.2f, 0.6f, -1e30f};
    int li = 3;
    float Tused = ladder[li];
    int n = 0;
    for (int attempt = 0; attempt < 8; attempt++) {
        if (tid == 0) s_n = 0;
        __syncthreads();
        const float T = ladder[li];
        for (int i = tid; i < LL / 4; i += 256) {
            float4 v = r4[i];
            int base = i * 4;
            if (v.x > T) { int p = atomicAdd(&s_n, 1); if (p < NCAND) keys[p] = mk_key(v.x, base); }
            if (v.y > T) { int p = atomicAdd(&s_n, 1); if (p < NCAND) keys[p] = mk_key(v.y, base + 1); }
            if (v.z > T) { int p = atomicAdd(&s_n, 1); if (p < NCAND) keys[p] = mk_key(v.z, base + 2); }
            if (v.w > T) { int p = atomicAdd(&s_n, 1); if (p < NCAND) keys[p] = mk_key(v.w, base + 3); }
        }
        __syncthreads();
        n = s_n;
        Tused = T;
        bool ok = (n >= KK && n <= NCAND);
        if (ok) break;
        if (n > NCAND) { if (li > 0) li--; else break; }
        else           { if (li < 7) li++; else break; }
        __syncthreads();
    }
    if (n > NCAND) n = NCAND;
    const int npow = (n <= 512) ? 512 : NCAND;
    for (int i = n + tid; i < npow; i += 256) keys[i] = 0ULL;
    __syncthreads();

    for (int size = 2; size <= npow; size <<= 1) {
        for (int stride = size >> 1; stride > 0; stride >>= 1) {
            for (int i = tid; i < npow; i += 256) {
                int j = i ^ stride;
                if (j > i && j < npow) {
                    bool asc = ((i & size) == 0);
                    unsigned long long x = keys[i], y = keys[j];
                    if ((x > y) == asc) { keys[i] = y; keys[j] = x; }
                }
            }
            __syncthreads();
        }
    }

    // ---- boundary refinement ----
    __shared__ int s_certain, s_bandN;
    __shared__ int   bandIdx[BANDCAP];
    __shared__ float bandVal[BANDCAP];
    __shared__ double bandD[BANDCAP];
    __shared__ int pickSlot[KK];
    __shared__ double s_red[8];

    const float v64 = key_val(keys[npow - KK]);
    const float hiv = v64 + DELTA;
    const float lov = v64 - DELTA;
    if (tid == 0) { s_certain = 0; s_bandN = 0; }
    __syncthreads();

    int certLocal = 0;
    if (lov > Tused) {
        for (int i = tid; i < npow; i += 256) {
            unsigned long long kk = keys[i];
            float v = key_val(kk);
            if (v > hiv) certLocal++;
            else if (v > lov) {
                int p = atomicAdd(&s_bandN, 1);
                if (p < BANDCAP) { bandIdx[p] = key_idx(kk); bandVal[p] = v; }
            }
        }
    } else {
        for (int i = tid; i < LL; i += 256) {
            float v = r[i];
            if (v > hiv) certLocal++;
            else if (v > lov) {
                int p = atomicAdd(&s_bandN, 1);
                if (p < BANDCAP) { bandIdx[p] = i; bandVal[p] = v; }
            }
        }
    }
    {
        int c = certLocal;
#pragma unroll
        for (int o = 16; o > 0; o >>= 1) c += __shfl_down_sync(0xffffffffu, c, o);
        if ((tid & 31) == 0) atomicAdd(&s_certain, c);
    }
    __syncthreads();

    const int certain = s_certain;
    int bandN = s_bandN; if (bandN > BANDCAP) bandN = BANDCAP;
    const int need = KK - certain;

    if (bandN == need || need < 0 || need > bandN) {
        if (tid < KK) {
            unsigned long long kk = keys[npow - 1 - tid];
            float v = key_val(kk);
            g_tv[row * KK + tid] = v > 0.f ? v : 0.f;
            g_ti[row * KK + tid] = key_idx(kk);
        }
        return;
    }

    if (tid == 0) {
        for (int i = 1; i < bandN; i++) {
            int ki = bandIdx[i]; float kv = bandVal[i];
            int j = i - 1;
            while (j >= 0 && bandIdx[j] > ki) {
                bandIdx[j + 1] = bandIdx[j]; bandVal[j + 1] = bandVal[j]; j--;
            }
            bandIdx[j + 1] = ki; bandVal[j + 1] = kv;
        }
    }
    __syncthreads();

    const float* xb = g_xbar + (size_t)row * DD;
    for (int c = 0; c < bandN; c++) {
        const float* wrow = W_enc + (size_t)bandIdx[c] * DD;
        double part = 0.0;
        for (int d = tid * 4; d < DD; d += 256 * 4) {
            part += (double)xb[d + 0] * (double)wrow[d + 0]
                  + (double)xb[d + 1] * (double)wrow[d + 1]
                  + (double)xb[d + 2] * (double)wrow[d + 2]
                  + (double)xb[d + 3] * (double)wrow[d + 3];
        }
#pragma unroll
        for (int o = 16; o > 0; o >>= 1) part += __shfl_down_sync(0xffffffffu, part, o);
        if ((tid & 31) == 0) s_red[tid >> 5] = part;
        __syncthreads();
        if (tid == 0) {
            double tot = 0.0;
            for (int w = 0; w < 8; w++) tot += s_red[w];
            bandD[c] = tot + (double)b_enc[bandIdx[c]];
        }
        __syncthreads();
    }

    if (tid == 0) {
        unsigned taken = 0, taken2 = 0;
        for (int p = 0; p < need; p++) {
            int best = -1;
            for (int c = 0; c < bandN; c++) {
                bool used = (c < 32) ? ((taken >> c) & 1u) : ((taken2 >> (c - 32)) & 1u);
                if (used) continue;
                if (best < 0 || bandD[c] > bandD[best]) best = c;
            }
            if (best < 32) taken |= 1u << best; else taken2 |= 1u << (best - 32);
            pickSlot[p] = best;
        }
    }
    __syncthreads();

    if (tid < KK) {
        float v; int idx;
        if (tid < certain) {
            unsigned long long kk = keys[npow - 1 - tid];
            v = key_val(kk); idx = key_idx(kk);
        } else {
            int c = pickSlot[tid - certain];
            v = bandVal[c]; idx = bandIdx[c];
        }
        g_tv[row * KK + tid] = v > 0.f ? v : 0.f;
        g_ti[row * KK + tid] = idx;
    }
}

// ---------------- f: zero row + scatter relu(vals) ----------------
__global__ void k_scatter(float* __restrict__ f) {
    const int row = blockIdx.x;
    float4* fr = (float4*)(f + (size_t)row * LL);
    for (int i = threadIdx.x; i < LL / 4; i += blockDim.x)
        fr[i] = make_float4(0.f, 0.f, 0.f, 0.f);
    __syncthreads();
    if (threadIdx.x < KK) {
        f[(size_t)row * LL + g_ti[row * KK + threadIdx.x]] = g_tv[row * KK + threadIdx.x];
    }
}

// ---------------- decoder ----------------
__global__ __launch_bounds__(256)
void k_dec(const float* __restrict__ b_dec, float* __restrict__ xhat) {
    const int row = blockIdx.x;
    const int tid = threadIdx.x;
    __shared__ float sv[KK];
    __shared__ int si[KK];
    if (tid < KK) {
        sv[tid] = g_tv[row * KK + tid];
        si[tid] = g_ti[row * KK + tid];
    }
    __syncthreads();
    float4 acc = ((const float4*)b_dec)[tid];
#pragma unroll 4
    for (int j = 0; j < KK; j++) {
        float v = sv[j];
        float4 w = ((const float4*)(g_WdecT + (size_t)si[j] * DD))[tid];
        acc.x += v * w.x; acc.y += v * w.y; acc.z += v * w.z; acc.w += v * w.w;
    }
    ((float4*)(xhat + (size_t)row * DD))[tid] = acc;
}

// ---------------- launcher ----------------
extern "C" void kernel_launch(void* const* d_in, const int* in_sizes, int n_in,
                              void* d_out, int out_size) {
    const float* x     = (const float*)d_in[0];
    const float* W_enc = (const float*)d_in[1];
    const float* b_enc = (const float*)d_in[2];
    const float* W_dec = (const float*)d_in[3];
    const float* b_dec = (const float*)d_in[4];
    float* f    = (float*)d_out;
    float* xhat = f + (size_t)BB * LL;

    cudaFuncSetAttribute(k_gemm, cudaFuncAttributeMaxDynamicSharedMemorySize, GSMEM);

    k_prep_a<<<(BB * DD + 255) / 256, 256>>>(x, b_dec);
    k_prep_b<<<(LL * DD + 255) / 256, 256>>>(W_enc);
    k_transpose<<<dim3(LL / 32, DD / 32), dim3(32, 8)>>>(W_dec);
    k_gemm<<<dim3(BB / GM, LL / GN), 512, GSMEM>>>(b_enc, f);
    k_topk<<<BB, 256>>>(f, W_enc, b_enc);
    k_scatter<<<BB, 256>>>(f);
    k_dec<<<BB, 256>>>(b_dec, xhat);
}